// round 6
// baseline (speedup 1.0000x reference)
#include <cuda_runtime.h>

// LightLIF fused step:
//   i_t   = inputs @ w_in + z @ (w_rec with zero diagonal)
//   new_v = DECAY*v + (1-DECAY)*i_t - z*THR*DT
//   new_z = ((new_v - THR)/THR > THR) ? 1 : 0
// Output buffer = [new_z (B*N_REC) | new_v (B*N_REC)], fp32.
//
// Single fused fp32 SGEMM (A = [inputs | z], W = [w_in ; w_rec], K = 3072),
// diagonal handled by subtracting z[b][n]*w_rec[n][n] in the epilogue.

namespace lif {

constexpr int M    = 4096;   // batch
constexpr int N    = 2048;   // n_rec
constexpr int KIN  = 1024;   // n_in
constexpr int KTOT = 3072;   // n_in + n_rec

constexpr int BM = 128;
constexpr int BN = 128;
constexpr int BK = 16;
constexpr int TM = 8;
constexpr int TN = 8;
constexpr int NTHREADS = 256;
constexpr int KTILES = KTOT / BK;   // 192

__device__ __forceinline__ void tile_ptrs(
    const float* __restrict__ inputs, const float* __restrict__ z,
    const float* __restrict__ w_in,   const float* __restrict__ w_rec,
    int gk0,
    const float*& Aptr, int& lda, const float*& Wptr)
{
    // K tiles never straddle the 1024 boundary (1024 % BK == 0).
    if (gk0 < KIN) {
        Aptr = inputs + gk0;
        lda  = KIN;
        Wptr = w_in + (size_t)gk0 * N;
    } else {
        Aptr = z + (gk0 - KIN);
        lda  = N;
        Wptr = w_rec + (size_t)(gk0 - KIN) * N;
    }
}

}  // namespace lif

__global__ __launch_bounds__(lif::NTHREADS, 2)
void LightLIF_29300266893640_kernel(
    const float* __restrict__ inputs,
    const float* __restrict__ v_in,
    const float* __restrict__ z_in,
    const float* __restrict__ w_in,
    const float* __restrict__ w_rec,
    float* __restrict__ out)
{
    using namespace lif;

    // Constants matched to the reference (float32 arithmetic).
    const float DECAY  = 0.951229424500714f;   // float32(exp(-1/20))
    const float ONE_MD = 1.0f - DECAY;
    const float THR    = 0.615f;               // THR * DT, DT = 1

    __shared__ float As[2][BK][BM];   // A stored transposed: As[k][m]
    __shared__ float Bs[2][BK][BN];   // Bs[k][n]

    const int tid = threadIdx.x;
    const int tx  = tid & 15;     // column group (0..15)
    const int ty  = tid >> 4;     // row group    (0..15)
    const int block_row = blockIdx.y * BM;
    const int block_col = blockIdx.x * BN;

    // A tile loader: 128 rows x 16 cols = 512 float4.
    // float4 f = tid -> (row = tid>>2, col4 = tid&3); second at row+64.
    const int a_row = tid >> 2;          // 0..63
    const int a_col = (tid & 3) * 4;     // 0,4,8,12
    // W tile loader: 16 rows x 128 cols = 512 float4.
    // float4 f = tid -> (row = tid>>5, col4 = tid&31); second at row+8.
    const int b_row = tid >> 5;          // 0..7
    const int b_col = (tid & 31) * 4;    // 0..124

    float acc[TM][TN];
    #pragma unroll
    for (int i = 0; i < TM; ++i)
        #pragma unroll
        for (int j = 0; j < TN; ++j)
            acc[i][j] = 0.0f;

    const float* Aptr;
    const float* Wptr;
    int lda;

    // ---- prologue: load tile 0 into buffer 0 ----
    tile_ptrs(inputs, z_in, w_in, w_rec, 0, Aptr, lda, Wptr);
    float4 av0 = *(const float4*)(Aptr + (size_t)(block_row + a_row)      * lda + a_col);
    float4 av1 = *(const float4*)(Aptr + (size_t)(block_row + a_row + 64) * lda + a_col);
    float4 bv0 = *(const float4*)(Wptr + (size_t)(b_row)     * N + block_col + b_col);
    float4 bv1 = *(const float4*)(Wptr + (size_t)(b_row + 8) * N + block_col + b_col);

    int buf = 0;
    {
        As[buf][a_col + 0][a_row]      = av0.x;
        As[buf][a_col + 1][a_row]      = av0.y;
        As[buf][a_col + 2][a_row]      = av0.z;
        As[buf][a_col + 3][a_row]      = av0.w;
        As[buf][a_col + 0][a_row + 64] = av1.x;
        As[buf][a_col + 1][a_row + 64] = av1.y;
        As[buf][a_col + 2][a_row + 64] = av1.z;
        As[buf][a_col + 3][a_row + 64] = av1.w;
        *(float4*)&Bs[buf][b_row][b_col]     = bv0;
        *(float4*)&Bs[buf][b_row + 8][b_col] = bv1;
    }
    __syncthreads();

    // ---- main loop: 192 K-tiles, double buffered ----
    for (int kt = 0; kt < KTILES; ++kt) {
        const bool has_next = (kt + 1 < KTILES);
        if (has_next) {
            tile_ptrs(inputs, z_in, w_in, w_rec, (kt + 1) * BK, Aptr, lda, Wptr);
            av0 = *(const float4*)(Aptr + (size_t)(block_row + a_row)      * lda + a_col);
            av1 = *(const float4*)(Aptr + (size_t)(block_row + a_row + 64) * lda + a_col);
            bv0 = *(const float4*)(Wptr + (size_t)(b_row)     * N + block_col + b_col);
            bv1 = *(const float4*)(Wptr + (size_t)(b_row + 8) * N + block_col + b_col);
        }

        #pragma unroll
        for (int k = 0; k < BK; ++k) {
            float a[TM], b[TN];
            *(float4*)&a[0] = *(const float4*)&As[buf][k][ty * TM];
            *(float4*)&a[4] = *(const float4*)&As[buf][k][ty * TM + 4];
            *(float4*)&b[0] = *(const float4*)&Bs[buf][k][tx * TN];
            *(float4*)&b[4] = *(const float4*)&Bs[buf][k][tx * TN + 4];
            #pragma unroll
            for (int i = 0; i < TM; ++i)
                #pragma unroll
                for (int j = 0; j < TN; ++j)
                    acc[i][j] = fmaf(a[i], b[j], acc[i][j]);
        }

        if (has_next) {
            const int nb = buf ^ 1;
            As[nb][a_col + 0][a_row]      = av0.x;
            As[nb][a_col + 1][a_row]      = av0.y;
            As[nb][a_col + 2][a_row]      = av0.z;
            As[nb][a_col + 3][a_row]      = av0.w;
            As[nb][a_col + 0][a_row + 64] = av1.x;
            As[nb][a_col + 1][a_row + 64] = av1.y;
            As[nb][a_col + 2][a_row + 64] = av1.z;
            As[nb][a_col + 3][a_row + 64] = av1.w;
            *(float4*)&Bs[nb][b_row][b_col]     = bv0;
            *(float4*)&Bs[nb][b_row + 8][b_col] = bv1;
            __syncthreads();
            buf = nb;
        }
    }

    // ---- epilogue: diag subtract + LIF update + spike ----
    const int rg = block_row + ty * TM;
    const int cg = block_col + tx * TN;

    float diag[TN];
    #pragma unroll
    for (int j = 0; j < TN; ++j)
        diag[j] = w_rec[(size_t)(cg + j) * (N + 1)];   // w_rec[n][n]

    const size_t vout_off = (size_t)M * N;

    #pragma unroll
    for (int i = 0; i < TM; ++i) {
        const size_t base = (size_t)(rg + i) * N + cg;
        float4 z0 = *(const float4*)(z_in + base);
        float4 z1 = *(const float4*)(z_in + base + 4);
        float4 v0 = *(const float4*)(v_in + base);
        float4 v1 = *(const float4*)(v_in + base + 4);

        float zz[TN] = {z0.x, z0.y, z0.z, z0.w, z1.x, z1.y, z1.z, z1.w};
        float vv[TN] = {v0.x, v0.y, v0.z, v0.w, v1.x, v1.y, v1.z, v1.w};

        float oz[TN], ov[TN];
        #pragma unroll
        for (int j = 0; j < TN; ++j) {
            const float it = acc[i][j] - zz[j] * diag[j];           // remove diagonal term
            const float nv = DECAY * vv[j] + ONE_MD * it - zz[j] * THR;
            const float vs = (nv - THR) / THR;                       // match ref's division
            ov[j] = nv;
            oz[j] = (vs > THR) ? 1.0f : 0.0f;
        }

        *(float4*)(out + base)              = make_float4(oz[0], oz[1], oz[2], oz[3]);
        *(float4*)(out + base + 4)          = make_float4(oz[4], oz[5], oz[6], oz[7]);
        *(float4*)(out + vout_off + base)     = make_float4(ov[0], ov[1], ov[2], ov[3]);
        *(float4*)(out + vout_off + base + 4) = make_float4(ov[4], ov[5], ov[6], ov[7]);
    }
}

extern "C" void kernel_launch(void* const* d_in, const int* in_sizes, int n_in,
                              void* d_out, int out_size)
{
    (void)in_sizes; (void)n_in; (void)out_size;
    const float* inputs = (const float*)d_in[0];   // [4096, 1024]
    const float* v      = (const float*)d_in[1];   // [4096, 2048]
    const float* z      = (const float*)d_in[2];   // [4096, 2048]
    const float* w_in   = (const float*)d_in[3];   // [1024, 2048]
    const float* w_rec  = (const float*)d_in[4];   // [2048, 2048]
    float* out = (float*)d_out;                    // [2, 4096, 2048] (z then v)

    dim3 grid(lif::N / lif::BN, lif::M / lif::BM);  // (16, 32)
    dim3 block(lif::NTHREADS);
    LightLIF_29300266893640_kernel<<<grid, block>>>(inputs, v, z, w_in, w_rec, out);
}

// round 12
// speedup vs baseline: 1.0291x; 1.0291x over previous
#include <cuda_runtime.h>
#include <cstdint>

// ============================================================================
// LightLIF via 2-way TF32-split GEMM on mma.sync (tcgen05 unavailable: harness
// builds virtual arch compute_103, accelerated features need the 'a' suffix).
//   C = Ahi*Bhi + Alo*Bhi + Ahi*Blo     (lo*lo dropped, ~1e-7 in i_t)
//   A = [inputs | z] (4096 x 3072),  Bt = [w_in ; w_rec]^T (2048 x 3072)
// Hard threshold tolerates ZERO spike flips (1 flip = 1.15e-3 rel err), so a
// fixup pass recomputes all borderline elements (|vs-THR| < 6e-3, ~10k elems)
// in double precision from the contiguous transposed weights.
// ============================================================================

namespace lif {
constexpr int M    = 4096;
constexpr int N    = 2048;
constexpr int KIN  = 1024;
constexpr int KTOT = 3072;

constexpr int BM = 128;
constexpr int BN = 128;
constexpr int BK = 32;                 // K per stage
constexpr int NKK = KTOT / BK;         // 96 stages
constexpr int NSTAGE = 3;

constexpr int TILE_SZ  = BM * BK * 4;  // 16384 B (128 rows x 128 B)
constexpr int SLOT_SZ  = 4 * TILE_SZ;  // Ahi | Alo | Bhi | Blo = 64 KB
constexpr int DIAG_OFF = NSTAGE * SLOT_SZ;         // 196608
constexpr int SMEM_TOTAL = DIAG_OFF + BN * 4;      // 197120

constexpr int   FIX_CAP = 1 << 20;
constexpr float EPS_VS  = 6e-3f;       // borderline window in v_scaled units

constexpr float DECAYF = 0.951229424500714f;   // float32(exp(-1/20))
constexpr float THRF   = 0.615f;
}  // namespace lif

// -------- scratch (device globals; no runtime allocation) --------
__device__ float g_Ahi[(size_t)lif::M * lif::KTOT];
__device__ float g_Alo[(size_t)lif::M * lif::KTOT];
__device__ float g_Bhi[(size_t)lif::N * lif::KTOT];   // transposed: [n][k]
__device__ float g_Blo[(size_t)lif::N * lif::KTOT];
__device__ int   g_fix_count;
__device__ int   g_fix_idx[lif::FIX_CAP];

// -------- helpers --------
__device__ __forceinline__ uint32_t smem_u32(const void* p) {
    uint32_t a;
    asm("{ .reg .u64 t; cvta.to.shared.u64 t, %1; cvt.u32.u64 %0, t; }" : "=r"(a) : "l"(p));
    return a;
}
__device__ __forceinline__ float tf32_rna(float x) {
    uint32_t r;
    asm("cvt.rna.tf32.f32 %0, %1;" : "=r"(r) : "f"(x));
    return __uint_as_float(r);
}
__device__ __forceinline__ void cp_async16(uint32_t smem, const void* g) {
    asm volatile("cp.async.cg.shared.global [%0], [%1], 16;" :: "r"(smem), "l"(g) : "memory");
}
#define CP_COMMIT() asm volatile("cp.async.commit_group;" ::: "memory")
#define CP_WAIT(n)  asm volatile("cp.async.wait_group %0;" :: "n"(n) : "memory")

__device__ __forceinline__ uint32_t sw128(uint32_t off) { return off ^ ((off >> 3) & 0x70); }

__device__ __forceinline__ void ldsm_x4(uint32_t r[4], uint32_t addr) {
    asm volatile("ldmatrix.sync.aligned.m8n8.x4.shared.b16 {%0,%1,%2,%3}, [%4];"
        : "=r"(r[0]), "=r"(r[1]), "=r"(r[2]), "=r"(r[3]) : "r"(addr));
}
// A fragment for m16n8k8 tf32 (validated by R8's 1e-3-level numerics).
__device__ __forceinline__ void ldsm_a(uint32_t r[4], uint32_t tile, int mbase, int ks, int lane) {
    uint32_t row = (uint32_t)(mbase + (lane & 15));
    uint32_t col = (uint32_t)(ks * 32 + ((lane >> 4) & 1) * 16);
    ldsm_x4(r, tile + sw128(row * 128 + col));
}
// B fragments for two n-octets, one k-slice.
__device__ __forceinline__ void ldsm_b(uint32_t r[4], uint32_t tile, int nbase, int ks, int lane) {
    uint32_t row = (uint32_t)(nbase + (lane & 7) + ((lane >> 4) & 1) * 8);
    uint32_t col = (uint32_t)(ks * 32 + ((lane >> 3) & 1) * 16);
    ldsm_x4(r, tile + sw128(row * 128 + col));
}
__device__ __forceinline__ void mma_tf32(float c[4], const uint32_t a[4], uint32_t b0, uint32_t b1) {
    asm volatile(
        "mma.sync.aligned.m16n8k8.row.col.f32.tf32.tf32.f32 "
        "{%0,%1,%2,%3}, {%4,%5,%6,%7}, {%8,%9}, {%0,%1,%2,%3};"
        : "+f"(c[0]), "+f"(c[1]), "+f"(c[2]), "+f"(c[3])
        : "r"(a[0]), "r"(a[1]), "r"(a[2]), "r"(a[3]), "r"(b0), "r"(b1));
}

// ============================================================================
// Pass 0: reset fixup counter (graph-safe, every call).
// ============================================================================
__global__ void lif_reset() { g_fix_count = 0; }

// ============================================================================
// Pass 1a: split A = [inputs | z] into tf32 hi/lo.
// ============================================================================
__global__ __launch_bounds__(256) void lif_conv_a(
    const float* __restrict__ inputs, const float* __restrict__ z)
{
    using namespace lif;
    size_t i4 = (size_t)blockIdx.x * blockDim.x + threadIdx.x;
    int m   = (int)(i4 / (KTOT / 4));
    int col = (int)(i4 % (KTOT / 4)) * 4;
    const float* src = (col < KIN) ? inputs + (size_t)m * KIN + col
                                   : z + (size_t)m * N + (col - KIN);
    float4 x = *(const float4*)src;
    float4 hi, lo;
    hi.x = tf32_rna(x.x); lo.x = tf32_rna(x.x - hi.x);
    hi.y = tf32_rna(x.y); lo.y = tf32_rna(x.y - hi.y);
    hi.z = tf32_rna(x.z); lo.z = tf32_rna(x.z - hi.z);
    hi.w = tf32_rna(x.w); lo.w = tf32_rna(x.w - hi.w);
    size_t dst = (size_t)m * KTOT + col;
    *(float4*)(g_Ahi + dst) = hi;
    *(float4*)(g_Alo + dst) = lo;
}

// ============================================================================
// Pass 1b: Bt[n][k] = split(W[k][n]) — transpose via smem tile.
// ============================================================================
__global__ __launch_bounds__(256) void lif_conv_b(
    const float* __restrict__ w_in, const float* __restrict__ w_rec)
{
    using namespace lif;
    __shared__ float t[32][33];
    const int k0 = blockIdx.x * 32;
    const int n0 = blockIdx.y * 32;
    const int tx = threadIdx.x, ty = threadIdx.y;   // block (32, 8)

    #pragma unroll
    for (int i = 0; i < 4; ++i) {
        int k = k0 + ty + i * 8;
        float w = (k < KIN) ? w_in[(size_t)k * N + n0 + tx]
                            : w_rec[(size_t)(k - KIN) * N + n0 + tx];
        t[ty + i * 8][tx] = w;
    }
    __syncthreads();
    #pragma unroll
    for (int i = 0; i < 4; ++i) {
        int n  = n0 + ty + i * 8;
        float x  = t[tx][ty + i * 8];
        float hi = tf32_rna(x);
        float lo = tf32_rna(x - hi);
        size_t dst = (size_t)n * KTOT + k0 + tx;
        g_Bhi[dst] = hi;
        g_Blo[dst] = lo;
    }
}

// ============================================================================
// Pass 2: pipelined mma.sync GEMM (128x128x32 stages) + fused LIF epilogue
// with borderline detection.
// ============================================================================
__global__ __launch_bounds__(256, 1) void lif_gemm(
    const float* __restrict__ v_in,
    const float* __restrict__ z_in,
    const float* __restrict__ w_rec,
    float* __restrict__ out)
{
    using namespace lif;
    extern __shared__ char smem[];
    const uint32_t sbase = smem_u32(smem);

    const int tid  = threadIdx.x;
    const int lane = tid & 31;
    const int wid  = tid >> 5;
    const int wm   = wid >> 1;           // 0..3 (M)
    const int wn   = wid & 1;            // 0..1 (N)

    const int row0A = blockIdx.y * BM;
    const int row0B = blockIdx.x * BN;

    float* sdiag = (float*)(smem + DIAG_OFF);
    if (tid < BN) sdiag[tid] = w_rec[(size_t)(row0B + tid) * (N + 1)];

    float acc[2][8][4];
    #pragma unroll
    for (int mt = 0; mt < 2; ++mt)
        #pragma unroll
        for (int nt = 0; nt < 8; ++nt)
            #pragma unroll
            for (int q = 0; q < 4; ++q) acc[mt][nt][q] = 0.0f;

    auto load_stage = [&](int kk, int st) {
        const uint32_t sb = sbase + st * SLOT_SZ;
        const int k0 = kk * BK;
        #pragma unroll
        for (int i = 0; i < 16; ++i) {
            const int u   = tid + i * 256;
            const int t   = u >> 10;           // 0:Ahi 1:Alo 2:Bhi 3:Blo
            const int w   = u & 1023;
            const int row = w >> 3;
            const int kq  = w & 7;
            const float* src;
            if (t == 0)      src = g_Ahi + (size_t)(row0A + row) * KTOT + k0 + kq * 4;
            else if (t == 1) src = g_Alo + (size_t)(row0A + row) * KTOT + k0 + kq * 4;
            else if (t == 2) src = g_Bhi + (size_t)(row0B + row) * KTOT + k0 + kq * 4;
            else             src = g_Blo + (size_t)(row0B + row) * KTOT + k0 + kq * 4;
            cp_async16(sb + t * TILE_SZ + sw128((uint32_t)(row * 128 + kq * 16)), src);
        }
        CP_COMMIT();
    };

    load_stage(0, 0);
    load_stage(1, 1);

    for (int kk = 0; kk < NKK; ++kk) {
        if (kk + 2 < NKK) { load_stage(kk + 2, (kk + 2) % NSTAGE); CP_WAIT(2); }
        else if (kk + 1 < NKK) { CP_WAIT(1); }
        else { CP_WAIT(0); }
        __syncthreads();

        const uint32_t sb   = sbase + (kk % NSTAGE) * SLOT_SZ;
        const uint32_t sAhi = sb;
        const uint32_t sAlo = sb + TILE_SZ;
        const uint32_t sBhi = sb + 2 * TILE_SZ;
        const uint32_t sBlo = sb + 3 * TILE_SZ;

        #pragma unroll
        for (int ks = 0; ks < 4; ++ks) {
            uint32_t ahi[2][4], alo[2][4], bhi[4][4], blo[4][4];

            ldsm_a(ahi[0], sAhi, wm * 32,      ks, lane);
            ldsm_a(ahi[1], sAhi, wm * 32 + 16, ks, lane);
            #pragma unroll
            for (int oc = 0; oc < 4; ++oc)
                ldsm_b(bhi[oc], sBhi, wn * 64 + oc * 16, ks, lane);

            #pragma unroll
            for (int mt = 0; mt < 2; ++mt)
                #pragma unroll
                for (int nt = 0; nt < 8; ++nt)
                    mma_tf32(acc[mt][nt], ahi[mt],
                             bhi[nt >> 1][2 * (nt & 1)], bhi[nt >> 1][2 * (nt & 1) + 1]);

            ldsm_a(alo[0], sAlo, wm * 32,      ks, lane);
            ldsm_a(alo[1], sAlo, wm * 32 + 16, ks, lane);
            #pragma unroll
            for (int mt = 0; mt < 2; ++mt)
                #pragma unroll
                for (int nt = 0; nt < 8; ++nt)
                    mma_tf32(acc[mt][nt], alo[mt],
                             bhi[nt >> 1][2 * (nt & 1)], bhi[nt >> 1][2 * (nt & 1) + 1]);

            #pragma unroll
            for (int oc = 0; oc < 4; ++oc)
                ldsm_b(blo[oc], sBlo, wn * 64 + oc * 16, ks, lane);
            #pragma unroll
            for (int mt = 0; mt < 2; ++mt)
                #pragma unroll
                for (int nt = 0; nt < 8; ++nt)
                    mma_tf32(acc[mt][nt], ahi[mt],
                             blo[nt >> 1][2 * (nt & 1)], blo[nt >> 1][2 * (nt & 1) + 1]);
        }
        __syncthreads();
    }

    // ---- fused LIF epilogue + borderline capture ----
    const float ONE_MD = 1.0f - DECAYF;
    const size_t vout_off = (size_t)M * N;

    const int qrow = lane >> 2;
    const int qcol = 2 * (lane & 3);

    #pragma unroll
    for (int mt = 0; mt < 2; ++mt) {
        #pragma unroll
        for (int half = 0; half < 2; ++half) {
            const int r = row0A + wm * 32 + mt * 16 + qrow + half * 8;
            #pragma unroll
            for (int nt = 0; nt < 8; ++nt) {
                const int cl = wn * 64 + nt * 8 + qcol;
                const int c  = row0B + cl;
                const size_t g = (size_t)r * N + c;

                const float2 zz = *(const float2*)(z_in + g);
                const float2 vv = *(const float2*)(v_in + g);
                const float a0 = acc[mt][nt][half * 2 + 0];
                const float a1 = acc[mt][nt][half * 2 + 1];

                const float it0 = a0 - zz.x * sdiag[cl];
                const float it1 = a1 - zz.y * sdiag[cl + 1];
                const float nv0 = DECAYF * vv.x + ONE_MD * it0 - zz.x * THRF;
                const float nv1 = DECAYF * vv.y + ONE_MD * it1 - zz.y * THRF;
                const float vs0 = (nv0 - THRF) / THRF;
                const float vs1 = (nv1 - THRF) / THRF;

                *(float2*)(out + g) = make_float2(vs0 > THRF ? 1.0f : 0.0f,
                                                  vs1 > THRF ? 1.0f : 0.0f);
                *(float2*)(out + vout_off + g) = make_float2(nv0, nv1);

                if (fabsf(vs0 - THRF) < EPS_VS) {
                    int s = atomicAdd(&g_fix_count, 1);
                    if (s < FIX_CAP) g_fix_idx[s] = (int)g;
                }
                if (fabsf(vs1 - THRF) < EPS_VS) {
                    int s = atomicAdd(&g_fix_count, 1);
                    if (s < FIX_CAP) g_fix_idx[s] = (int)(g + 1);
                }
            }
        }
    }
}

// ============================================================================
// Pass 3: double-precision recompute of borderline elements. One warp/element.
// Weights read from the contiguous transposed hi/lo split (hi+lo == w to 2^-23).
// ============================================================================
__global__ __launch_bounds__(256) void lif_fixup(
    const float* __restrict__ inputs,
    const float* __restrict__ v_in,
    const float* __restrict__ z_in,
    const float* __restrict__ w_rec,
    float* __restrict__ out)
{
    using namespace lif;
    const int gtid  = blockIdx.x * blockDim.x + threadIdx.x;
    const int warp  = gtid >> 5;
    const int lane  = gtid & 31;
    const int nwarp = (gridDim.x * blockDim.x) >> 5;

    int cnt = g_fix_count;
    if (cnt > FIX_CAP) cnt = FIX_CAP;

    const double DECAY_D  = (double)DECAYF;
    const double ONE_MD_D = (double)(1.0f - DECAYF);
    const double THR_D    = (double)THRF;
    const size_t vout_off = (size_t)M * N;

    for (int e = warp; e < cnt; e += nwarp) {
        const int idx = g_fix_idx[e];
        const int b = idx / N;
        const int n = idx - b * N;

        const float* bh = g_Bhi + (size_t)n * KTOT;
        const float* bl = g_Blo + (size_t)n * KTOT;
        const float* ai = inputs + (size_t)b * KIN;
        const float* az = z_in   + (size_t)b * N;

        double acc = 0.0;
        for (int k = lane; k < KIN; k += 32)
            acc += (double)ai[k] * ((double)bh[k] + (double)bl[k]);
        for (int k = lane; k < N; k += 32)
            acc += (double)az[k] * ((double)bh[KIN + k] + (double)bl[KIN + k]);
        #pragma unroll
        for (int o = 16; o; o >>= 1)
            acc += __shfl_down_sync(0xFFFFFFFFu, acc, o);

        if (lane == 0) {
            const double zd = (double)z_in[idx];
            const double it = acc - zd * (double)w_rec[(size_t)n * (N + 1)];
            const double nv = DECAY_D * (double)v_in[idx] + ONE_MD_D * it - zd * THR_D;
            const double vs = (nv - THR_D) / THR_D;
            out[idx]            = (vs > THR_D) ? 1.0f : 0.0f;
            out[vout_off + idx] = (float)nv;
        }
    }
}

// ============================================================================
extern "C" void kernel_launch(void* const* d_in, const int* in_sizes, int n_in,
                              void* d_out, int out_size)
{
    (void)in_sizes; (void)n_in; (void)out_size;
    using namespace lif;
    const float* inputs = (const float*)d_in[0];   // [4096, 1024]
    const float* v      = (const float*)d_in[1];   // [4096, 2048]
    const float* z      = (const float*)d_in[2];   // [4096, 2048]
    const float* w_in   = (const float*)d_in[3];   // [1024, 2048]
    const float* w_rec  = (const float*)d_in[4];   // [2048, 2048]
    float* out = (float*)d_out;                    // [2, 4096, 2048] (z then v)

    static bool attr_set = false;
    if (!attr_set) {
        cudaFuncSetAttribute(lif_gemm, cudaFuncAttributeMaxDynamicSharedMemorySize, SMEM_TOTAL);
        attr_set = true;
    }

    lif_reset<<<1, 1>>>();
    lif_conv_a<<<(M * KTOT / 4) / 256, 256>>>(inputs, z);
    lif_conv_b<<<dim3(KTOT / 32, N / 32), dim3(32, 8)>>>(w_in, w_rec);
    lif_gemm<<<dim3(N / BN, M / BM), 256, SMEM_TOTAL>>>(v, z, w_rec, out);
    lif_fixup<<<512, 256>>>(inputs, v, z, w_rec, out);
}

// round 13
// speedup vs baseline: 1.4358x; 1.3952x over previous
#include <cuda_runtime.h>
#include <cstdint>

// ============================================================================
// LightLIF via 2-way TF32-split GEMM on mma.sync (tcgen05 unavailable: harness
// builds virtual arch compute_103; accelerated features need the 'a' suffix).
//   C = Ahi*Bhi + Alo*Bhi + Ahi*Blo     (lo*lo dropped, ~1e-7 in i_t)
//   A = [inputs | z] (4096 x 3072),  Bt = [w_in ; w_rec]^T (2048 x 3072)
// Hard threshold tolerates ZERO spike flips, so borderline elements
// (|vs-THR| < 2e-4, ~500 elems) are recomputed in double precision.
// R13: 512-thread GEMM CTA (16 warps, 4x4, warp tile 32x32) to feed the tensor
// pipe (R12: tensor=60.6% @ 8 warps); fixup window 6e-3 -> 2e-4; reset folded
// into conv_a.
// ============================================================================

namespace lif {
constexpr int M    = 4096;
constexpr int N    = 2048;
constexpr int KIN  = 1024;
constexpr int KTOT = 3072;

constexpr int BM = 128;
constexpr int BN = 128;
constexpr int BK = 32;                 // K per stage
constexpr int NKK = KTOT / BK;         // 96 stages
constexpr int NSTAGE = 3;
constexpr int NTHR = 512;              // 16 warps

constexpr int TILE_SZ  = BM * BK * 4;  // 16384 B (128 rows x 128 B)
constexpr int SLOT_SZ  = 4 * TILE_SZ;  // Ahi | Alo | Bhi | Blo = 64 KB
constexpr int DIAG_OFF = NSTAGE * SLOT_SZ;         // 196608
constexpr int SMEM_TOTAL = DIAG_OFF + BN * 4;      // 197120

constexpr int   FIX_CAP = 1 << 20;
constexpr float EPS_VS  = 2e-4f;       // borderline window in v_scaled units
                                       // (worst-case combined error ~7e-6)

constexpr float DECAYF = 0.951229424500714f;   // float32(exp(-1/20))
constexpr float THRF   = 0.615f;
}  // namespace lif

// -------- scratch (device globals; no runtime allocation) --------
__device__ float g_Ahi[(size_t)lif::M * lif::KTOT];
__device__ float g_Alo[(size_t)lif::M * lif::KTOT];
__device__ float g_Bhi[(size_t)lif::N * lif::KTOT];   // transposed: [n][k]
__device__ float g_Blo[(size_t)lif::N * lif::KTOT];
__device__ int   g_fix_count;
__device__ int   g_fix_idx[lif::FIX_CAP];

// -------- helpers --------
__device__ __forceinline__ uint32_t smem_u32(const void* p) {
    uint32_t a;
    asm("{ .reg .u64 t; cvta.to.shared.u64 t, %1; cvt.u32.u64 %0, t; }" : "=r"(a) : "l"(p));
    return a;
}
__device__ __forceinline__ float tf32_rna(float x) {
    uint32_t r;
    asm("cvt.rna.tf32.f32 %0, %1;" : "=r"(r) : "f"(x));
    return __uint_as_float(r);
}
__device__ __forceinline__ void cp_async16(uint32_t smem, const void* g) {
    asm volatile("cp.async.cg.shared.global [%0], [%1], 16;" :: "r"(smem), "l"(g) : "memory");
}
#define CP_COMMIT() asm volatile("cp.async.commit_group;" ::: "memory")
#define CP_WAIT(n)  asm volatile("cp.async.wait_group %0;" :: "n"(n) : "memory")

__device__ __forceinline__ uint32_t sw128(uint32_t off) { return off ^ ((off >> 3) & 0x70); }

__device__ __forceinline__ void ldsm_x4(uint32_t r[4], uint32_t addr) {
    asm volatile("ldmatrix.sync.aligned.m8n8.x4.shared.b16 {%0,%1,%2,%3}, [%4];"
        : "=r"(r[0]), "=r"(r[1]), "=r"(r[2]), "=r"(r[3]) : "r"(addr));
}
// A fragment for m16n8k8 tf32 (numerics validated R11/R12).
__device__ __forceinline__ void ldsm_a(uint32_t r[4], uint32_t tile, int mbase, int ks, int lane) {
    uint32_t row = (uint32_t)(mbase + (lane & 15));
    uint32_t col = (uint32_t)(ks * 32 + ((lane >> 4) & 1) * 16);
    ldsm_x4(r, tile + sw128(row * 128 + col));
}
// B fragments for two n-octets (16 cols), one k-slice.
__device__ __forceinline__ void ldsm_b(uint32_t r[4], uint32_t tile, int nbase, int ks, int lane) {
    uint32_t row = (uint32_t)(nbase + (lane & 7) + ((lane >> 4) & 1) * 8);
    uint32_t col = (uint32_t)(ks * 32 + ((lane >> 3) & 1) * 16);
    ldsm_x4(r, tile + sw128(row * 128 + col));
}
__device__ __forceinline__ void mma_tf32(float c[4], const uint32_t a[4], uint32_t b0, uint32_t b1) {
    asm volatile(
        "mma.sync.aligned.m16n8k8.row.col.f32.tf32.tf32.f32 "
        "{%0,%1,%2,%3}, {%4,%5,%6,%7}, {%8,%9}, {%0,%1,%2,%3};"
        : "+f"(c[0]), "+f"(c[1]), "+f"(c[2]), "+f"(c[3])
        : "r"(a[0]), "r"(a[1]), "r"(a[2]), "r"(a[3]), "r"(b0), "r"(b1));
}

// ============================================================================
// Pass 1a: split A = [inputs | z] into tf32 hi/lo. Also resets fixup counter
// (same-stream ordering: this kernel completes before lif_gemm starts).
// ============================================================================
__global__ __launch_bounds__(256) void lif_conv_a(
    const float* __restrict__ inputs, const float* __restrict__ z)
{
    using namespace lif;
    if (blockIdx.x == 0 && threadIdx.x == 0) g_fix_count = 0;

    size_t i4 = (size_t)blockIdx.x * blockDim.x + threadIdx.x;
    int m   = (int)(i4 / (KTOT / 4));
    int col = (int)(i4 % (KTOT / 4)) * 4;
    const float* src = (col < KIN) ? inputs + (size_t)m * KIN + col
                                   : z + (size_t)m * N + (col - KIN);
    float4 x = *(const float4*)src;
    float4 hi, lo;
    hi.x = tf32_rna(x.x); lo.x = tf32_rna(x.x - hi.x);
    hi.y = tf32_rna(x.y); lo.y = tf32_rna(x.y - hi.y);
    hi.z = tf32_rna(x.z); lo.z = tf32_rna(x.z - hi.z);
    hi.w = tf32_rna(x.w); lo.w = tf32_rna(x.w - hi.w);
    size_t dst = (size_t)m * KTOT + col;
    *(float4*)(g_Ahi + dst) = hi;
    *(float4*)(g_Alo + dst) = lo;
}

// ============================================================================
// Pass 1b: Bt[n][k] = split(W[k][n]) — transpose via smem tile.
// ============================================================================
__global__ __launch_bounds__(256) void lif_conv_b(
    const float* __restrict__ w_in, const float* __restrict__ w_rec)
{
    using namespace lif;
    __shared__ float t[32][33];
    const int k0 = blockIdx.x * 32;
    const int n0 = blockIdx.y * 32;
    const int tx = threadIdx.x, ty = threadIdx.y;   // block (32, 8)

    #pragma unroll
    for (int i = 0; i < 4; ++i) {
        int k = k0 + ty + i * 8;
        float w = (k < KIN) ? w_in[(size_t)k * N + n0 + tx]
                            : w_rec[(size_t)(k - KIN) * N + n0 + tx];
        t[ty + i * 8][tx] = w;
    }
    __syncthreads();
    #pragma unroll
    for (int i = 0; i < 4; ++i) {
        int n  = n0 + ty + i * 8;
        float x  = t[tx][ty + i * 8];
        float hi = tf32_rna(x);
        float lo = tf32_rna(x - hi);
        size_t dst = (size_t)n * KTOT + k0 + tx;
        g_Bhi[dst] = hi;
        g_Blo[dst] = lo;
    }
}

// ============================================================================
// Pass 2: pipelined mma.sync GEMM, 16 warps (4x4), warp tile 32x32,
// 128x128x32 stages + fused LIF epilogue with borderline detection.
// ============================================================================
__global__ __launch_bounds__(lif::NTHR, 1) void lif_gemm(
    const float* __restrict__ v_in,
    const float* __restrict__ z_in,
    const float* __restrict__ w_rec,
    float* __restrict__ out)
{
    using namespace lif;
    extern __shared__ char smem[];
    const uint32_t sbase = smem_u32(smem);

    const int tid  = threadIdx.x;
    const int lane = tid & 31;
    const int wid  = tid >> 5;
    const int wm   = wid >> 2;           // 0..3 (M): 32-row band
    const int wn   = wid & 3;            // 0..3 (N): 32-col band

    const int row0A = blockIdx.y * BM;
    const int row0B = blockIdx.x * BN;

    float* sdiag = (float*)(smem + DIAG_OFF);
    if (tid < BN) sdiag[tid] = w_rec[(size_t)(row0B + tid) * (N + 1)];

    float acc[2][4][4];
    #pragma unroll
    for (int mt = 0; mt < 2; ++mt)
        #pragma unroll
        for (int nt = 0; nt < 4; ++nt)
            #pragma unroll
            for (int q = 0; q < 4; ++q) acc[mt][nt][q] = 0.0f;

    // ---- stage loader: 4 tiles x 1024 x 16B = 4096 units, 8 per thread ----
    auto load_stage = [&](int kk, int st) {
        const uint32_t sb = sbase + st * SLOT_SZ;
        const int k0 = kk * BK;
        #pragma unroll
        for (int i = 0; i < 8; ++i) {
            const int u   = tid + i * NTHR;
            const int t   = u >> 10;           // 0:Ahi 1:Alo 2:Bhi 3:Blo
            const int w   = u & 1023;
            const int row = w >> 3;
            const int kq  = w & 7;
            const float* src;
            if (t == 0)      src = g_Ahi + (size_t)(row0A + row) * KTOT + k0 + kq * 4;
            else if (t == 1) src = g_Alo + (size_t)(row0A + row) * KTOT + k0 + kq * 4;
            else if (t == 2) src = g_Bhi + (size_t)(row0B + row) * KTOT + k0 + kq * 4;
            else             src = g_Blo + (size_t)(row0B + row) * KTOT + k0 + kq * 4;
            cp_async16(sb + t * TILE_SZ + sw128((uint32_t)(row * 128 + kq * 16)), src);
        }
        CP_COMMIT();
    };

    load_stage(0, 0);
    load_stage(1, 1);

    for (int kk = 0; kk < NKK; ++kk) {
        if (kk + 2 < NKK) { load_stage(kk + 2, (kk + 2) % NSTAGE); CP_WAIT(2); }
        else if (kk + 1 < NKK) { CP_WAIT(1); }
        else { CP_WAIT(0); }
        __syncthreads();

        const uint32_t sb   = sbase + (kk % NSTAGE) * SLOT_SZ;
        const uint32_t sAhi = sb;
        const uint32_t sAlo = sb + TILE_SZ;
        const uint32_t sBhi = sb + 2 * TILE_SZ;
        const uint32_t sBlo = sb + 3 * TILE_SZ;

        #pragma unroll
        for (int ks = 0; ks < 4; ++ks) {
            uint32_t ahi[2][4], alo[2][4], bhi[2][4], blo[2][4];

            ldsm_a(ahi[0], sAhi, wm * 32,      ks, lane);
            ldsm_a(ahi[1], sAhi, wm * 32 + 16, ks, lane);
            ldsm_b(bhi[0], sBhi, wn * 32,      ks, lane);
            ldsm_b(bhi[1], sBhi, wn * 32 + 16, ks, lane);

            #pragma unroll
            for (int mt = 0; mt < 2; ++mt)
                #pragma unroll
                for (int nt = 0; nt < 4; ++nt)
                    mma_tf32(acc[mt][nt], ahi[mt],
                             bhi[nt >> 1][2 * (nt & 1)], bhi[nt >> 1][2 * (nt & 1) + 1]);

            ldsm_a(alo[0], sAlo, wm * 32,      ks, lane);
            ldsm_a(alo[1], sAlo, wm * 32 + 16, ks, lane);
            #pragma unroll
            for (int mt = 0; mt < 2; ++mt)
                #pragma unroll
                for (int nt = 0; nt < 4; ++nt)
                    mma_tf32(acc[mt][nt], alo[mt],
                             bhi[nt >> 1][2 * (nt & 1)], bhi[nt >> 1][2 * (nt & 1) + 1]);

            ldsm_b(blo[0], sBlo, wn * 32,      ks, lane);
            ldsm_b(blo[1], sBlo, wn * 32 + 16, ks, lane);
            #pragma unroll
            for (int mt = 0; mt < 2; ++mt)
                #pragma unroll
                for (int nt = 0; nt < 4; ++nt)
                    mma_tf32(acc[mt][nt], ahi[mt],
                             blo[nt >> 1][2 * (nt & 1)], blo[nt >> 1][2 * (nt & 1) + 1]);
        }
        __syncthreads();
    }

    // ---- fused LIF epilogue + borderline capture ----
    const float ONE_MD = 1.0f - DECAYF;
    const size_t vout_off = (size_t)M * N;

    const int qrow = lane >> 2;
    const int qcol = 2 * (lane & 3);

    #pragma unroll
    for (int mt = 0; mt < 2; ++mt) {
        #pragma unroll
        for (int half = 0; half < 2; ++half) {
            const int r = row0A + wm * 32 + mt * 16 + qrow + half * 8;
            #pragma unroll
            for (int nt = 0; nt < 4; ++nt) {
                const int cl = wn * 32 + nt * 8 + qcol;
                const int c  = row0B + cl;
                const size_t g = (size_t)r * N + c;

                const float2 zz = *(const float2*)(z_in + g);
                const float2 vv = *(const float2*)(v_in + g);
                const float a0 = acc[mt][nt][half * 2 + 0];
                const float a1 = acc[mt][nt][half * 2 + 1];

                const float it0 = a0 - zz.x * sdiag[cl];
                const float it1 = a1 - zz.y * sdiag[cl + 1];
                const float nv0 = DECAYF * vv.x + ONE_MD * it0 - zz.x * THRF;
                const float nv1 = DECAYF * vv.y + ONE_MD * it1 - zz.y * THRF;
                const float vs0 = (nv0 - THRF) / THRF;
                const float vs1 = (nv1 - THRF) / THRF;

                *(float2*)(out + g) = make_float2(vs0 > THRF ? 1.0f : 0.0f,
                                                  vs1 > THRF ? 1.0f : 0.0f);
                *(float2*)(out + vout_off + g) = make_float2(nv0, nv1);

                if (fabsf(vs0 - THRF) < EPS_VS) {
                    int s = atomicAdd(&g_fix_count, 1);
                    if (s < FIX_CAP) g_fix_idx[s] = (int)g;
                }
                if (fabsf(vs1 - THRF) < EPS_VS) {
                    int s = atomicAdd(&g_fix_count, 1);
                    if (s < FIX_CAP) g_fix_idx[s] = (int)(g + 1);
                }
            }
        }
    }
}

// ============================================================================
// Pass 3: double-precision recompute of borderline elements. One warp/element.
// ============================================================================
__global__ __launch_bounds__(256) void lif_fixup(
    const float* __restrict__ inputs,
    const float* __restrict__ v_in,
    const float* __restrict__ z_in,
    const float* __restrict__ w_rec,
    float* __restrict__ out)
{
    using namespace lif;
    const int gtid  = blockIdx.x * blockDim.x + threadIdx.x;
    const int warp  = gtid >> 5;
    const int lane  = gtid & 31;
    const int nwarp = (gridDim.x * blockDim.x) >> 5;

    int cnt = g_fix_count;
    if (cnt > FIX_CAP) cnt = FIX_CAP;

    const double DECAY_D  = (double)DECAYF;
    const double ONE_MD_D = (double)(1.0f - DECAYF);
    const double THR_D    = (double)THRF;
    const size_t vout_off = (size_t)M * N;

    for (int e = warp; e < cnt; e += nwarp) {
        const int idx = g_fix_idx[e];
        const int b = idx / N;
        const int n = idx - b * N;

        const float* bh = g_Bhi + (size_t)n * KTOT;
        const float* bl = g_Blo + (size_t)n * KTOT;
        const float* ai = inputs + (size_t)b * KIN;
        const float* az = z_in   + (size_t)b * N;

        double acc = 0.0;
        for (int k = lane; k < KIN; k += 32)
            acc += (double)ai[k] * ((double)bh[k] + (double)bl[k]);
        for (int k = lane; k < N; k += 32)
            acc += (double)az[k] * ((double)bh[KIN + k] + (double)bl[KIN + k]);
        #pragma unroll
        for (int o = 16; o; o >>= 1)
            acc += __shfl_down_sync(0xFFFFFFFFu, acc, o);

        if (lane == 0) {
            const double zd = (double)z_in[idx];
            const double it = acc - zd * (double)w_rec[(size_t)n * (N + 1)];
            const double nv = DECAY_D * (double)v_in[idx] + ONE_MD_D * it - zd * THR_D;
            const double vs = (nv - THR_D) / THR_D;
            out[idx]            = (vs > THR_D) ? 1.0f : 0.0f;
            out[vout_off + idx] = (float)nv;
        }
    }
}

// ============================================================================
extern "C" void kernel_launch(void* const* d_in, const int* in_sizes, int n_in,
                              void* d_out, int out_size)
{
    (void)in_sizes; (void)n_in; (void)out_size;
    using namespace lif;
    const float* inputs = (const float*)d_in[0];   // [4096, 1024]
    const float* v      = (const float*)d_in[1];   // [4096, 2048]
    const float* z      = (const float*)d_in[2];   // [4096, 2048]
    const float* w_in   = (const float*)d_in[3];   // [1024, 2048]
    const float* w_rec  = (const float*)d_in[4];   // [2048, 2048]
    float* out = (float*)d_out;                    // [2, 4096, 2048] (z then v)

    static bool attr_set = false;
    if (!attr_set) {
        cudaFuncSetAttribute(lif_gemm, cudaFuncAttributeMaxDynamicSharedMemorySize, SMEM_TOTAL);
        attr_set = true;
    }

    lif_conv_a<<<(M * KTOT / 4) / 256, 256>>>(inputs, z);
    lif_conv_b<<<dim3(KTOT / 32, N / 32), dim3(32, 8)>>>(w_in, w_rec);
    lif_gemm<<<dim3(N / BN, M / BM), NTHR, SMEM_TOTAL>>>(v, z, w_rec, out);
    lif_fixup<<<256, 256>>>(inputs, v, z, w_rec, out);
}

// round 14
// speedup vs baseline: 3.0187x; 2.1024x over previous
#include <cuda_runtime.h>
#include <cstdint>

// ============================================================================
// LightLIF via SINGLE-product TF32 mma.sync GEMM + borderline DP fixup.
// R13 postmortem: 3-product split was tensor-issue+LDSM-crossbar bound; the
// hard threshold only needs exactness NEAR the threshold. So:
//   - GEMM: one tf32 pass (rna pre-rounded), error in v_scaled ~3e-5 rms.
//   - Every element with |v_scaled-THR| < 1.5e-3 (~3k elems, 50 sigma) is
//     recomputed in double precision from an exact fp32 W^T copy.
// CTA 128x256, 8 warps, warp tile 64x64 (ldsm:mma = 1:4 -> crossbar 50%).
// ============================================================================

namespace lif {
constexpr int M    = 4096;
constexpr int N    = 2048;
constexpr int KIN  = 1024;
constexpr int KTOT = 3072;

constexpr int BM = 128;
constexpr int BN = 256;
constexpr int BK = 32;                  // K per stage
constexpr int NKK = KTOT / BK;          // 96
constexpr int NSTAGE = 3;
constexpr int NTHR = 256;               // 8 warps: 2 (M) x 4 (N), tile 64x64

constexpr int A_TILE = BM * BK * 4;     // 16384 B
constexpr int B_TILE = BN * BK * 4;     // 32768 B
constexpr int SLOT_SZ = A_TILE + B_TILE;            // 49152 B
constexpr int DIAG_OFF = NSTAGE * SLOT_SZ;          // 147456
constexpr int SMEM_TOTAL = DIAG_OFF + BN * 4;       // 148480

constexpr int   FIX_CAP = 1 << 20;
constexpr float EPS_VS  = 1.5e-3f;      // borderline window (v_scaled units)

constexpr float DECAYF = 0.951229424500714f;   // float32(exp(-1/20))
constexpr float THRF   = 0.615f;
}  // namespace lif

// -------- scratch (device globals; no runtime allocation) --------
__device__ float g_Ahi[(size_t)lif::M * lif::KTOT];  // rna(tf32) of [inputs|z]
__device__ float g_Bhi[(size_t)lif::N * lif::KTOT];  // rna(tf32) of W^T
__device__ float g_Bt [(size_t)lif::N * lif::KTOT];  // exact fp32 W^T (fixup)
__device__ int   g_fix_count;
__device__ int   g_fix_idx[lif::FIX_CAP];

// -------- helpers --------
__device__ __forceinline__ uint32_t smem_u32(const void* p) {
    uint32_t a;
    asm("{ .reg .u64 t; cvta.to.shared.u64 t, %1; cvt.u32.u64 %0, t; }" : "=r"(a) : "l"(p));
    return a;
}
__device__ __forceinline__ float tf32_rna(float x) {
    uint32_t r;
    asm("cvt.rna.tf32.f32 %0, %1;" : "=r"(r) : "f"(x));
    return __uint_as_float(r);
}
__device__ __forceinline__ void cp_async16(uint32_t smem, const void* g) {
    asm volatile("cp.async.cg.shared.global [%0], [%1], 16;" :: "r"(smem), "l"(g) : "memory");
}
#define CP_COMMIT() asm volatile("cp.async.commit_group;" ::: "memory")
#define CP_WAIT(n)  asm volatile("cp.async.wait_group %0;" :: "n"(n) : "memory")

__device__ __forceinline__ uint32_t sw128(uint32_t off) { return off ^ ((off >> 3) & 0x70); }

__device__ __forceinline__ void ldsm_x4(uint32_t r[4], uint32_t addr) {
    asm volatile("ldmatrix.sync.aligned.m8n8.x4.shared.b16 {%0,%1,%2,%3}, [%4];"
        : "=r"(r[0]), "=r"(r[1]), "=r"(r[2]), "=r"(r[3]) : "r"(addr));
}
// A fragment (16 rows x 8 k) for m16n8k8 tf32 — layout validated R11..R13.
__device__ __forceinline__ void ldsm_a(uint32_t r[4], uint32_t tile, int mbase, int ks, int lane) {
    uint32_t row = (uint32_t)(mbase + (lane & 15));
    uint32_t col = (uint32_t)(ks * 32 + ((lane >> 4) & 1) * 16);
    ldsm_x4(r, tile + sw128(row * 128 + col));
}
// B fragments for two n-octets (16 cols), one k-slice.
__device__ __forceinline__ void ldsm_b(uint32_t r[4], uint32_t tile, int nbase, int ks, int lane) {
    uint32_t row = (uint32_t)(nbase + (lane & 7) + ((lane >> 4) & 1) * 8);
    uint32_t col = (uint32_t)(ks * 32 + ((lane >> 3) & 1) * 16);
    ldsm_x4(r, tile + sw128(row * 128 + col));
}
__device__ __forceinline__ void mma_tf32(float c[4], const uint32_t a[4], uint32_t b0, uint32_t b1) {
    asm volatile(
        "mma.sync.aligned.m16n8k8.row.col.f32.tf32.tf32.f32 "
        "{%0,%1,%2,%3}, {%4,%5,%6,%7}, {%8,%9}, {%0,%1,%2,%3};"
        : "+f"(c[0]), "+f"(c[1]), "+f"(c[2]), "+f"(c[3])
        : "r"(a[0]), "r"(a[1]), "r"(a[2]), "r"(a[3]), "r"(b0), "r"(b1));
}

// ============================================================================
// Pass 1a: Ahi = rna([inputs | z]); resets fixup counter (stream-ordered).
// ============================================================================
__global__ __launch_bounds__(256) void lif_conv_a(
    const float* __restrict__ inputs, const float* __restrict__ z)
{
    using namespace lif;
    if (blockIdx.x == 0 && threadIdx.x == 0) g_fix_count = 0;

    size_t i4 = (size_t)blockIdx.x * blockDim.x + threadIdx.x;
    int m   = (int)(i4 / (KTOT / 4));
    int col = (int)(i4 % (KTOT / 4)) * 4;
    const float* src = (col < KIN) ? inputs + (size_t)m * KIN + col
                                   : z + (size_t)m * N + (col - KIN);
    float4 x = *(const float4*)src;
    float4 hi;
    hi.x = tf32_rna(x.x);
    hi.y = tf32_rna(x.y);
    hi.z = tf32_rna(x.z);
    hi.w = tf32_rna(x.w);
    *(float4*)(g_Ahi + (size_t)m * KTOT + col) = hi;
}

// ============================================================================
// Pass 1b: W^T transpose: Bhi = rna(W^T), Bt = W^T exact (for the DP fixup).
// ============================================================================
__global__ __launch_bounds__(256) void lif_conv_b(
    const float* __restrict__ w_in, const float* __restrict__ w_rec)
{
    using namespace lif;
    __shared__ float t[32][33];
    const int k0 = blockIdx.x * 32;
    const int n0 = blockIdx.y * 32;
    const int tx = threadIdx.x, ty = threadIdx.y;   // block (32, 8)

    #pragma unroll
    for (int i = 0; i < 4; ++i) {
        int k = k0 + ty + i * 8;
        float w = (k < KIN) ? w_in[(size_t)k * N + n0 + tx]
                            : w_rec[(size_t)(k - KIN) * N + n0 + tx];
        t[ty + i * 8][tx] = w;
    }
    __syncthreads();
    #pragma unroll
    for (int i = 0; i < 4; ++i) {
        int n  = n0 + ty + i * 8;
        float x  = t[tx][ty + i * 8];
        size_t dst = (size_t)n * KTOT + k0 + tx;
        g_Bhi[dst] = tf32_rna(x);
        g_Bt[dst]  = x;
    }
}

// ============================================================================
// Pass 2: single-product tf32 GEMM. CTA 128x256x32, 3 stages, 8 warps (2x4),
// warp tile 64x64. Fused LIF epilogue + borderline capture.
// ============================================================================
__global__ __launch_bounds__(lif::NTHR, 1) void lif_gemm(
    const float* __restrict__ v_in,
    const float* __restrict__ z_in,
    const float* __restrict__ w_rec,
    float* __restrict__ out)
{
    using namespace lif;
    extern __shared__ char smem[];
    const uint32_t sbase = smem_u32(smem);

    const int tid  = threadIdx.x;
    const int lane = tid & 31;
    const int wid  = tid >> 5;
    const int wm   = wid & 1;            // 0..1 (M): 64-row band
    const int wn   = wid >> 1;           // 0..3 (N): 64-col band

    const int row0A = blockIdx.y * BM;
    const int row0B = blockIdx.x * BN;

    float* sdiag = (float*)(smem + DIAG_OFF);
    sdiag[tid] = w_rec[(size_t)(row0B + tid) * (N + 1)];   // 256 diag values

    float acc[4][8][4];
    #pragma unroll
    for (int mt = 0; mt < 4; ++mt)
        #pragma unroll
        for (int nt = 0; nt < 8; ++nt)
            #pragma unroll
            for (int q = 0; q < 4; ++q) acc[mt][nt][q] = 0.0f;

    // ---- stage loader: A 1024 + B 2048 16B-units = 12 cp.async / thread ----
    auto load_stage = [&](int kk, int st) {
        const uint32_t sb = sbase + st * SLOT_SZ;
        const int k0 = kk * BK;
        #pragma unroll
        for (int i = 0; i < 12; ++i) {
            const int u = tid + i * NTHR;
            if (i < 4) {                       // A tile: u in [0,1024)
                const int row = u >> 3, kq = u & 7;
                cp_async16(sb + sw128((uint32_t)(row * 128 + kq * 16)),
                           g_Ahi + (size_t)(row0A + row) * KTOT + k0 + kq * 4);
            } else {                           // B tile: u-1024 in [0,2048)
                const int ub = u - 1024;
                const int row = ub >> 3, kq = ub & 7;
                cp_async16(sb + A_TILE + sw128((uint32_t)(row * 128 + kq * 16)),
                           g_Bhi + (size_t)(row0B + row) * KTOT + k0 + kq * 4);
            }
        }
        CP_COMMIT();
    };

    load_stage(0, 0);
    load_stage(1, 1);

    for (int kk = 0; kk < NKK; ++kk) {
        if (kk + 2 < NKK) { load_stage(kk + 2, (kk + 2) % NSTAGE); CP_WAIT(2); }
        else if (kk + 1 < NKK) { CP_WAIT(1); }
        else { CP_WAIT(0); }
        __syncthreads();

        const uint32_t sb = sbase + (kk % NSTAGE) * SLOT_SZ;
        const uint32_t sA = sb;
        const uint32_t sB = sb + A_TILE;

        #pragma unroll
        for (int ks = 0; ks < 4; ++ks) {
            uint32_t a[4][4], b[4][4];
            #pragma unroll
            for (int mt = 0; mt < 4; ++mt)
                ldsm_a(a[mt], sA, wm * 64 + mt * 16, ks, lane);
            #pragma unroll
            for (int nb = 0; nb < 4; ++nb)
                ldsm_b(b[nb], sB, wn * 64 + nb * 16, ks, lane);

            #pragma unroll
            for (int mt = 0; mt < 4; ++mt)
                #pragma unroll
                for (int nt = 0; nt < 8; ++nt)
                    mma_tf32(acc[mt][nt], a[mt],
                             b[nt >> 1][2 * (nt & 1)], b[nt >> 1][2 * (nt & 1) + 1]);
        }
        __syncthreads();
    }

    // ---- fused LIF epilogue + borderline capture ----
    const float ONE_MD = 1.0f - DECAYF;
    const size_t vout_off = (size_t)M * N;

    const int qrow = lane >> 2;
    const int qcol = 2 * (lane & 3);

    #pragma unroll
    for (int mt = 0; mt < 4; ++mt) {
        #pragma unroll
        for (int half = 0; half < 2; ++half) {
            const int r = row0A + wm * 64 + mt * 16 + half * 8 + qrow;
            #pragma unroll
            for (int nt = 0; nt < 8; ++nt) {
                const int cl = wn * 64 + nt * 8 + qcol;
                const int c  = row0B + cl;
                const size_t g = (size_t)r * N + c;

                const float2 zz = *(const float2*)(z_in + g);
                const float2 vv = *(const float2*)(v_in + g);
                const float a0 = acc[mt][nt][half * 2 + 0];
                const float a1 = acc[mt][nt][half * 2 + 1];

                const float it0 = a0 - zz.x * sdiag[cl];
                const float it1 = a1 - zz.y * sdiag[cl + 1];
                const float nv0 = DECAYF * vv.x + ONE_MD * it0 - zz.x * THRF;
                const float nv1 = DECAYF * vv.y + ONE_MD * it1 - zz.y * THRF;
                const float vs0 = (nv0 - THRF) / THRF;
                const float vs1 = (nv1 - THRF) / THRF;

                *(float2*)(out + g) = make_float2(vs0 > THRF ? 1.0f : 0.0f,
                                                  vs1 > THRF ? 1.0f : 0.0f);
                *(float2*)(out + vout_off + g) = make_float2(nv0, nv1);

                if (fabsf(vs0 - THRF) < EPS_VS) {
                    int s = atomicAdd(&g_fix_count, 1);
                    if (s < FIX_CAP) g_fix_idx[s] = (int)g;
                }
                if (fabsf(vs1 - THRF) < EPS_VS) {
                    int s = atomicAdd(&g_fix_count, 1);
                    if (s < FIX_CAP) g_fix_idx[s] = (int)(g + 1);
                }
            }
        }
    }
}

// ============================================================================
// Pass 3: double-precision recompute of borderline elements (one warp each),
// reading the exact fp32 transposed weights.
// ============================================================================
__global__ __launch_bounds__(256) void lif_fixup(
    const float* __restrict__ inputs,
    const float* __restrict__ v_in,
    const float* __restrict__ z_in,
    const float* __restrict__ w_rec,
    float* __restrict__ out)
{
    using namespace lif;
    const int gtid  = blockIdx.x * blockDim.x + threadIdx.x;
    const int warp  = gtid >> 5;
    const int lane  = gtid & 31;
    const int nwarp = (gridDim.x * blockDim.x) >> 5;

    int cnt = g_fix_count;
    if (cnt > FIX_CAP) cnt = FIX_CAP;

    const double DECAY_D  = (double)DECAYF;
    const double ONE_MD_D = (double)(1.0f - DECAYF);
    const double THR_D    = (double)THRF;
    const size_t vout_off = (size_t)M * N;

    for (int e = warp; e < cnt; e += nwarp) {
        const int idx = g_fix_idx[e];
        const int b = idx / N;
        const int n = idx - b * N;

        const float* bt = g_Bt + (size_t)n * KTOT;
        const float* ai = inputs + (size_t)b * KIN;
        const float* az = z_in   + (size_t)b * N;

        double acc = 0.0;
        for (int k = lane; k < KIN; k += 32)
            acc += (double)ai[k] * (double)bt[k];
        for (int k = lane; k < N; k += 32)
            acc += (double)az[k] * (double)bt[KIN + k];
        #pragma unroll
        for (int o = 16; o; o >>= 1)
            acc += __shfl_down_sync(0xFFFFFFFFu, acc, o);

        if (lane == 0) {
            const double zd = (double)z_in[idx];
            const double it = acc - zd * (double)w_rec[(size_t)n * (N + 1)];
            const double nv = DECAY_D * (double)v_in[idx] + ONE_MD_D * it - zd * THR_D;
            const double vs = (nv - THR_D) / THR_D;
            out[idx]            = (vs > THR_D) ? 1.0f : 0.0f;
            out[vout_off + idx] = (float)nv;
        }
    }
}

// ============================================================================
extern "C" void kernel_launch(void* const* d_in, const int* in_sizes, int n_in,
                              void* d_out, int out_size)
{
    (void)in_sizes; (void)n_in; (void)out_size;
    using namespace lif;
    const float* inputs = (const float*)d_in[0];   // [4096, 1024]
    const float* v      = (const float*)d_in[1];   // [4096, 2048]
    const float* z      = (const float*)d_in[2];   // [4096, 2048]
    const float* w_in   = (const float*)d_in[3];   // [1024, 2048]
    const float* w_rec  = (const float*)d_in[4];   // [2048, 2048]
    float* out = (float*)d_out;                    // [2, 4096, 2048] (z then v)

    static bool attr_set = false;
    if (!attr_set) {
        cudaFuncSetAttribute(lif_gemm, cudaFuncAttributeMaxDynamicSharedMemorySize, SMEM_TOTAL);
        attr_set = true;
    }

    lif_conv_a<<<(M * KTOT / 4) / 256, 256>>>(inputs, z);
    lif_conv_b<<<dim3(KTOT / 32, N / 32), dim3(32, 8)>>>(w_in, w_rec);
    lif_gemm<<<dim3(N / BN, M / BM), NTHR, SMEM_TOTAL>>>(v, z, w_rec, out);
    lif_fixup<<<512, 256>>>(inputs, v, z, w_rec, out);
}

// round 15
// speedup vs baseline: 3.5916x; 1.1898x over previous
#include <cuda_runtime.h>
#include <cuda_bf16.h>
#include <cstdint>

// ============================================================================
// LightLIF via single-pass BF16 mma.sync GEMM + borderline DP fixup.
// R14 finding: gemm throughput is HMMA *instruction-issue* bound (186 T-MAC/s
// for both 1-product and 3-product tf32). bf16 m16n8k16 packs 2048 MAC/inst
// (2x tf32 m16n8k8) -> ~2x gemm speedup at the same issue rate.
// Numerics: bf16 single-pass rel_err(new_v) ~1.3e-4 (< 1e-3, measured-scaled
// from tf32's 1.6e-5). Spikes: every element with |v_scaled-THR| < 3e-3
// (~14 sigma, ~9k elems) recomputed in double precision -> zero flips.
// ============================================================================

namespace lif {
constexpr int M    = 4096;
constexpr int N    = 2048;
constexpr int KIN  = 1024;
constexpr int KTOT = 3072;

constexpr int BM = 128;
constexpr int BN = 256;
constexpr int BK = 64;                  // bf16 K per stage (128B rows)
constexpr int NKK = KTOT / BK;          // 48
constexpr int NSTAGE = 3;
constexpr int NTHR = 256;               // 8 warps: 2 (M) x 4 (N), tile 64x64

constexpr int A_TILE = BM * BK * 2;     // 16384 B
constexpr int B_TILE = BN * BK * 2;     // 32768 B
constexpr int SLOT_SZ = A_TILE + B_TILE;            // 49152 B
constexpr int DIAG_OFF = NSTAGE * SLOT_SZ;          // 147456
constexpr int SMEM_TOTAL = DIAG_OFF + BN * 4;       // 148480

constexpr int   FIX_CAP = 1 << 20;
constexpr float EPS_VS  = 3e-3f;        // ~14 sigma of bf16 v_scaled error

constexpr float DECAYF = 0.951229424500714f;   // float32(exp(-1/20))
constexpr float THRF   = 0.615f;
}  // namespace lif

// -------- scratch (device globals; no runtime allocation) --------
__device__ __nv_bfloat16 g_Abf[(size_t)lif::M * lif::KTOT];  // rn(bf16) [inputs|z]
__device__ __nv_bfloat16 g_Bbf[(size_t)lif::N * lif::KTOT];  // rn(bf16) W^T
__device__ float         g_Bt [(size_t)lif::N * lif::KTOT];  // exact fp32 W^T
__device__ int           g_fix_count;
__device__ int           g_fix_idx[lif::FIX_CAP];

// -------- helpers --------
__device__ __forceinline__ uint32_t smem_u32(const void* p) {
    uint32_t a;
    asm("{ .reg .u64 t; cvta.to.shared.u64 t, %1; cvt.u32.u64 %0, t; }" : "=r"(a) : "l"(p));
    return a;
}
__device__ __forceinline__ void cp_async16(uint32_t smem, const void* g) {
    asm volatile("cp.async.cg.shared.global [%0], [%1], 16;" :: "r"(smem), "l"(g) : "memory");
}
#define CP_COMMIT() asm volatile("cp.async.commit_group;" ::: "memory")
#define CP_WAIT(n)  asm volatile("cp.async.wait_group %0;" :: "n"(n) : "memory")

__device__ __forceinline__ uint32_t sw128(uint32_t off) { return off ^ ((off >> 3) & 0x70); }

__device__ __forceinline__ void ldsm_x4(uint32_t r[4], uint32_t addr) {
    asm volatile("ldmatrix.sync.aligned.m8n8.x4.shared.b16 {%0,%1,%2,%3}, [%4];"
        : "=r"(r[0]), "=r"(r[1]), "=r"(r[2]), "=r"(r[3]) : "r"(addr));
}
// A fragment (16 rows x k16) for m16n8k16 bf16: mats = (m0-7,k0-7),(m8-15,k0-7),
// (m0-7,k8-15),(m8-15,k8-15) -> regs a0..a3 match the mma A fragment.
__device__ __forceinline__ void ldsm_a(uint32_t r[4], uint32_t tile, int mbase, int ks, int lane) {
    uint32_t row = (uint32_t)(mbase + (lane & 15));
    uint32_t col = (uint32_t)(ks * 32 + ((lane >> 4) & 1) * 16);   // k16 = 32B
    ldsm_x4(r, tile + sw128(row * 128 + col));
}
// B fragments for two n-octets, one k16 slice: mats = (n0-7,k0-7),(n0-7,k8-15),
// (n8-15,k0-7),(n8-15,k8-15) -> r0=b0(oct0), r1=b1(oct0), r2=b0(oct1), r3=b1(oct1).
__device__ __forceinline__ void ldsm_b(uint32_t r[4], uint32_t tile, int nbase, int ks, int lane) {
    uint32_t row = (uint32_t)(nbase + (lane & 7) + ((lane >> 4) & 1) * 8);
    uint32_t col = (uint32_t)(ks * 32 + ((lane >> 3) & 1) * 16);
    ldsm_x4(r, tile + sw128(row * 128 + col));
}
__device__ __forceinline__ void mma_bf16(float c[4], const uint32_t a[4], uint32_t b0, uint32_t b1) {
    asm volatile(
        "mma.sync.aligned.m16n8k16.row.col.f32.bf16.bf16.f32 "
        "{%0,%1,%2,%3}, {%4,%5,%6,%7}, {%8,%9}, {%0,%1,%2,%3};"
        : "+f"(c[0]), "+f"(c[1]), "+f"(c[2]), "+f"(c[3])
        : "r"(a[0]), "r"(a[1]), "r"(a[2]), "r"(a[3]), "r"(b0), "r"(b1));
}

// ============================================================================
// Pass 1a: Abf = bf16_rn([inputs | z]); resets fixup counter (stream-ordered).
// ============================================================================
__global__ __launch_bounds__(256) void lif_conv_a(
    const float* __restrict__ inputs, const float* __restrict__ z)
{
    using namespace lif;
    if (blockIdx.x == 0 && threadIdx.x == 0) g_fix_count = 0;

    size_t i4 = (size_t)blockIdx.x * blockDim.x + threadIdx.x;
    int m   = (int)(i4 / (KTOT / 4));
    int col = (int)(i4 % (KTOT / 4)) * 4;
    const float* src = (col < KIN) ? inputs + (size_t)m * KIN + col
                                   : z + (size_t)m * N + (col - KIN);
    float4 x = *(const float4*)src;
    __nv_bfloat162 lo = __nv_bfloat162(__float2bfloat16_rn(x.x), __float2bfloat16_rn(x.y));
    __nv_bfloat162 hi = __nv_bfloat162(__float2bfloat16_rn(x.z), __float2bfloat16_rn(x.w));
    uint2 packed;
    packed.x = *(uint32_t*)&lo;
    packed.y = *(uint32_t*)&hi;
    *(uint2*)(g_Abf + (size_t)m * KTOT + col) = packed;
}

// ============================================================================
// Pass 1b: W^T transpose: Bbf = bf16_rn(W^T), Bt = exact fp32 W^T (fixup).
// ============================================================================
__global__ __launch_bounds__(256) void lif_conv_b(
    const float* __restrict__ w_in, const float* __restrict__ w_rec)
{
    using namespace lif;
    __shared__ float t[32][33];
    const int k0 = blockIdx.x * 32;
    const int n0 = blockIdx.y * 32;
    const int tx = threadIdx.x, ty = threadIdx.y;   // block (32, 8)

    #pragma unroll
    for (int i = 0; i < 4; ++i) {
        int k = k0 + ty + i * 8;
        float w = (k < KIN) ? w_in[(size_t)k * N + n0 + tx]
                            : w_rec[(size_t)(k - KIN) * N + n0 + tx];
        t[ty + i * 8][tx] = w;
    }
    __syncthreads();
    #pragma unroll
    for (int i = 0; i < 4; ++i) {
        int n  = n0 + ty + i * 8;
        float x  = t[tx][ty + i * 8];
        size_t dst = (size_t)n * KTOT + k0 + tx;
        g_Bbf[dst] = __float2bfloat16_rn(x);
        g_Bt[dst]  = x;
    }
}

// ============================================================================
// Pass 2: single-pass bf16 GEMM. CTA 128x256x64, 3 stages, 8 warps (2x4),
// warp tile 64x64, one barrier per stage. Fused LIF epilogue + capture.
// ============================================================================
__global__ __launch_bounds__(lif::NTHR, 1) void lif_gemm(
    const float* __restrict__ v_in,
    const float* __restrict__ z_in,
    const float* __restrict__ w_rec,
    float* __restrict__ out)
{
    using namespace lif;
    extern __shared__ char smem[];
    const uint32_t sbase = smem_u32(smem);

    const int tid  = threadIdx.x;
    const int lane = tid & 31;
    const int wid  = tid >> 5;
    const int wm   = wid & 1;            // 0..1 (M): 64-row band
    const int wn   = wid >> 1;           // 0..3 (N): 64-col band

    const int row0A = blockIdx.y * BM;
    const int row0B = blockIdx.x * BN;

    float* sdiag = (float*)(smem + DIAG_OFF);
    sdiag[tid] = w_rec[(size_t)(row0B + tid) * (N + 1)];

    float acc[4][8][4];
    #pragma unroll
    for (int mt = 0; mt < 4; ++mt)
        #pragma unroll
        for (int nt = 0; nt < 8; ++nt)
            #pragma unroll
            for (int q = 0; q < 4; ++q) acc[mt][nt][q] = 0.0f;

    // ---- stage loader: A 1024 + B 2048 16B-units = 12 cp.async / thread ----
    auto load_stage = [&](int kk, int st) {
        const uint32_t sb = sbase + st * SLOT_SZ;
        const int k0 = kk * BK;            // bf16 element offset
        #pragma unroll
        for (int i = 0; i < 12; ++i) {
            const int u = tid + i * NTHR;
            if (i < 4) {                   // A tile: u in [0,1024)
                const int row = u >> 3, kq = u & 7;
                cp_async16(sb + sw128((uint32_t)(row * 128 + kq * 16)),
                           g_Abf + (size_t)(row0A + row) * KTOT + k0 + kq * 8);
            } else {                       // B tile: u-1024 in [0,2048)
                const int ub = u - 1024;
                const int row = ub >> 3, kq = ub & 7;
                cp_async16(sb + A_TILE + sw128((uint32_t)(row * 128 + kq * 16)),
                           g_Bbf + (size_t)(row0B + row) * KTOT + k0 + kq * 8);
            }
        }
        CP_COMMIT();
    };

    load_stage(0, 0);
    load_stage(1, 1);

    for (int kk = 0; kk < NKK; ++kk) {
        if (kk + 1 < NKK) { CP_WAIT(1); } else { CP_WAIT(0); }
        __syncthreads();   // (a) stage kk visible to all; (b) all done with kk-1
        if (kk + 2 < NKK) load_stage(kk + 2, (kk + 2) % NSTAGE);

        const uint32_t sb = sbase + (kk % NSTAGE) * SLOT_SZ;
        const uint32_t sA = sb;
        const uint32_t sB = sb + A_TILE;

        #pragma unroll
        for (int ks = 0; ks < 4; ++ks) {   // 4 x k16 = 64 K per stage
            uint32_t a[4][4], b[4][4];
            #pragma unroll
            for (int mt = 0; mt < 4; ++mt)
                ldsm_a(a[mt], sA, wm * 64 + mt * 16, ks, lane);
            #pragma unroll
            for (int nb = 0; nb < 4; ++nb)
                ldsm_b(b[nb], sB, wn * 64 + nb * 16, ks, lane);

            #pragma unroll
            for (int mt = 0; mt < 4; ++mt)
                #pragma unroll
                for (int nt = 0; nt < 8; ++nt)
                    mma_bf16(acc[mt][nt], a[mt],
                             b[nt >> 1][2 * (nt & 1)], b[nt >> 1][2 * (nt & 1) + 1]);
        }
    }

    // ---- fused LIF epilogue + borderline capture ----
    const float ONE_MD = 1.0f - DECAYF;
    const size_t vout_off = (size_t)M * N;

    const int qrow = lane >> 2;
    const int qcol = 2 * (lane & 3);

    #pragma unroll
    for (int mt = 0; mt < 4; ++mt) {
        #pragma unroll
        for (int half = 0; half < 2; ++half) {
            const int r = row0A + wm * 64 + mt * 16 + half * 8 + qrow;
            #pragma unroll
            for (int nt = 0; nt < 8; ++nt) {
                const int cl = wn * 64 + nt * 8 + qcol;
                const int c  = row0B + cl;
                const size_t g = (size_t)r * N + c;

                const float2 zz = *(const float2*)(z_in + g);
                const float2 vv = *(const float2*)(v_in + g);
                const float a0 = acc[mt][nt][half * 2 + 0];
                const float a1 = acc[mt][nt][half * 2 + 1];

                const float it0 = a0 - zz.x * sdiag[cl];
                const float it1 = a1 - zz.y * sdiag[cl + 1];
                const float nv0 = DECAYF * vv.x + ONE_MD * it0 - zz.x * THRF;
                const float nv1 = DECAYF * vv.y + ONE_MD * it1 - zz.y * THRF;
                const float vs0 = (nv0 - THRF) / THRF;
                const float vs1 = (nv1 - THRF) / THRF;

                *(float2*)(out + g) = make_float2(vs0 > THRF ? 1.0f : 0.0f,
                                                  vs1 > THRF ? 1.0f : 0.0f);
                *(float2*)(out + vout_off + g) = make_float2(nv0, nv1);

                if (fabsf(vs0 - THRF) < EPS_VS) {
                    int s = atomicAdd(&g_fix_count, 1);
                    if (s < FIX_CAP) g_fix_idx[s] = (int)g;
                }
                if (fabsf(vs1 - THRF) < EPS_VS) {
                    int s = atomicAdd(&g_fix_count, 1);
                    if (s < FIX_CAP) g_fix_idx[s] = (int)(g + 1);
                }
            }
        }
    }
}

// ============================================================================
// Pass 3: DP recompute of borderline elements — one warp each, 4 independent
// accumulators to break the DFMA dependency chain (R14: 107us, chain-bound).
// ============================================================================
__global__ __launch_bounds__(256) void lif_fixup(
    const float* __restrict__ inputs,
    const float* __restrict__ v_in,
    const float* __restrict__ z_in,
    const float* __restrict__ w_rec,
    float* __restrict__ out)
{
    using namespace lif;
    const int gtid  = blockIdx.x * blockDim.x + threadIdx.x;
    const int warp  = gtid >> 5;
    const int lane  = gtid & 31;
    const int nwarp = (gridDim.x * blockDim.x) >> 5;

    int cnt = g_fix_count;
    if (cnt > FIX_CAP) cnt = FIX_CAP;

    const double DECAY_D  = (double)DECAYF;
    const double ONE_MD_D = (double)(1.0f - DECAYF);
    const double THR_D    = (double)THRF;
    const size_t vout_off = (size_t)M * N;

    for (int e = warp; e < cnt; e += nwarp) {
        const int idx = g_fix_idx[e];
        const int b = idx / N;
        const int n = idx - b * N;

        const float* bt = g_Bt + (size_t)n * KTOT;
        const float* ai = inputs + (size_t)b * KIN;
        const float* az = z_in   + (size_t)b * N;

        double a0 = 0.0, a1 = 0.0, a2 = 0.0, a3 = 0.0;
        for (int k = lane; k < KIN; k += 128) {   // 1024 = 8 x 128
            a0 += (double)ai[k]      * (double)bt[k];
            a1 += (double)ai[k + 32] * (double)bt[k + 32];
            a2 += (double)ai[k + 64] * (double)bt[k + 64];
            a3 += (double)ai[k + 96] * (double)bt[k + 96];
        }
        for (int k = lane; k < N; k += 128) {     // 2048 = 16 x 128
            a0 += (double)az[k]      * (double)bt[KIN + k];
            a1 += (double)az[k + 32] * (double)bt[KIN + k + 32];
            a2 += (double)az[k + 64] * (double)bt[KIN + k + 64];
            a3 += (double)az[k + 96] * (double)bt[KIN + k + 96];
        }
        double acc = (a0 + a1) + (a2 + a3);
        #pragma unroll
        for (int o = 16; o; o >>= 1)
            acc += __shfl_down_sync(0xFFFFFFFFu, acc, o);

        if (lane == 0) {
            const double zd = (double)z_in[idx];
            const double it = acc - zd * (double)w_rec[(size_t)n * (N + 1)];
            const double nv = DECAY_D * (double)v_in[idx] + ONE_MD_D * it - zd * THR_D;
            const double vs = (nv - THR_D) / THR_D;
            out[idx]            = (vs > THR_D) ? 1.0f : 0.0f;
            out[vout_off + idx] = (float)nv;
        }
    }
}

// ============================================================================
extern "C" void kernel_launch(void* const* d_in, const int* in_sizes, int n_in,
                              void* d_out, int out_size)
{
    (void)in_sizes; (void)n_in; (void)out_size;
    using namespace lif;
    const float* inputs = (const float*)d_in[0];   // [4096, 1024]
    const float* v      = (const float*)d_in[1];   // [4096, 2048]
    const float* z      = (const float*)d_in[2];   // [4096, 2048]
    const float* w_in   = (const float*)d_in[3];   // [1024, 2048]
    const float* w_rec  = (const float*)d_in[4];   // [2048, 2048]
    float* out = (float*)d_out;                    // [2, 4096, 2048] (z then v)

    static bool attr_set = false;
    if (!attr_set) {
        cudaFuncSetAttribute(lif_gemm, cudaFuncAttributeMaxDynamicSharedMemorySize, SMEM_TOTAL);
        attr_set = true;
    }

    lif_conv_a<<<(M * KTOT / 4) / 256, 256>>>(inputs, z);
    lif_conv_b<<<dim3(KTOT / 32, N / 32), dim3(32, 8)>>>(w_in, w_rec);
    lif_gemm<<<dim3(N / BN, M / BM), NTHR, SMEM_TOTAL>>>(v, z, w_rec, out);
    lif_fixup<<<512, 256>>>(inputs, v, z, w_rec, out);
}

// round 16
// speedup vs baseline: 3.9455x; 1.0985x over previous
#include <cuda_runtime.h>
#include <cuda_bf16.h>
#include <cstdint>

// ============================================================================
// LightLIF via single-pass BF16 mma.sync GEMM + borderline DP fixup.
// R15: gemm ~170us is the mma.sync bf16 HMMA-pipe floor (0.556 inst/SM/cyc,
// warp-count invariant). Fixup was 158us (latency-bound scalar gather).
// R16: fixup rewritten -- float4 loads (48 LDG.128 vs 192 LDG.32 per element),
// 2 independent DP accumulators, window 3e-3 -> 2e-3 (9.5 sigma, ~3.9k elems).
// ============================================================================

namespace lif {
constexpr int M    = 4096;
constexpr int N    = 2048;
constexpr int KIN  = 1024;
constexpr int KTOT = 3072;

constexpr int BM = 128;
constexpr int BN = 256;
constexpr int BK = 64;                  // bf16 K per stage (128B rows)
constexpr int NKK = KTOT / BK;          // 48
constexpr int NSTAGE = 3;
constexpr int NTHR = 256;               // 8 warps: 2 (M) x 4 (N), tile 64x64

constexpr int A_TILE = BM * BK * 2;     // 16384 B
constexpr int B_TILE = BN * BK * 2;     // 32768 B
constexpr int SLOT_SZ = A_TILE + B_TILE;            // 49152 B
constexpr int DIAG_OFF = NSTAGE * SLOT_SZ;          // 147456
constexpr int SMEM_TOTAL = DIAG_OFF + BN * 4;       // 148480

constexpr int   FIX_CAP = 1 << 20;
constexpr float EPS_VS  = 2e-3f;        // 9.5 sigma of measured bf16 vs-error

constexpr float DECAYF = 0.951229424500714f;   // float32(exp(-1/20))
constexpr float THRF   = 0.615f;
}  // namespace lif

// -------- scratch (device globals; no runtime allocation) --------
__device__ __nv_bfloat16 g_Abf[(size_t)lif::M * lif::KTOT];  // rn(bf16) [inputs|z]
__device__ __nv_bfloat16 g_Bbf[(size_t)lif::N * lif::KTOT];  // rn(bf16) W^T
__device__ float         g_Bt [(size_t)lif::N * lif::KTOT];  // exact fp32 W^T
__device__ int           g_fix_count;
__device__ int           g_fix_idx[lif::FIX_CAP];

// -------- helpers --------
__device__ __forceinline__ uint32_t smem_u32(const void* p) {
    uint32_t a;
    asm("{ .reg .u64 t; cvta.to.shared.u64 t, %1; cvt.u32.u64 %0, t; }" : "=r"(a) : "l"(p));
    return a;
}
__device__ __forceinline__ void cp_async16(uint32_t smem, const void* g) {
    asm volatile("cp.async.cg.shared.global [%0], [%1], 16;" :: "r"(smem), "l"(g) : "memory");
}
#define CP_COMMIT() asm volatile("cp.async.commit_group;" ::: "memory")
#define CP_WAIT(n)  asm volatile("cp.async.wait_group %0;" :: "n"(n) : "memory")

__device__ __forceinline__ uint32_t sw128(uint32_t off) { return off ^ ((off >> 3) & 0x70); }

__device__ __forceinline__ void ldsm_x4(uint32_t r[4], uint32_t addr) {
    asm volatile("ldmatrix.sync.aligned.m8n8.x4.shared.b16 {%0,%1,%2,%3}, [%4];"
        : "=r"(r[0]), "=r"(r[1]), "=r"(r[2]), "=r"(r[3]) : "r"(addr));
}
// A fragment (16 rows x k16) for m16n8k16 bf16 — layout validated R15.
__device__ __forceinline__ void ldsm_a(uint32_t r[4], uint32_t tile, int mbase, int ks, int lane) {
    uint32_t row = (uint32_t)(mbase + (lane & 15));
    uint32_t col = (uint32_t)(ks * 32 + ((lane >> 4) & 1) * 16);
    ldsm_x4(r, tile + sw128(row * 128 + col));
}
// B fragments for two n-octets, one k16 slice.
__device__ __forceinline__ void ldsm_b(uint32_t r[4], uint32_t tile, int nbase, int ks, int lane) {
    uint32_t row = (uint32_t)(nbase + (lane & 7) + ((lane >> 4) & 1) * 8);
    uint32_t col = (uint32_t)(ks * 32 + ((lane >> 3) & 1) * 16);
    ldsm_x4(r, tile + sw128(row * 128 + col));
}
__device__ __forceinline__ void mma_bf16(float c[4], const uint32_t a[4], uint32_t b0, uint32_t b1) {
    asm volatile(
        "mma.sync.aligned.m16n8k16.row.col.f32.bf16.bf16.f32 "
        "{%0,%1,%2,%3}, {%4,%5,%6,%7}, {%8,%9}, {%0,%1,%2,%3};"
        : "+f"(c[0]), "+f"(c[1]), "+f"(c[2]), "+f"(c[3])
        : "r"(a[0]), "r"(a[1]), "r"(a[2]), "r"(a[3]), "r"(b0), "r"(b1));
}

// ============================================================================
// Pass 1a: Abf = bf16_rn([inputs | z]); resets fixup counter (stream-ordered).
// ============================================================================
__global__ __launch_bounds__(256) void lif_conv_a(
    const float* __restrict__ inputs, const float* __restrict__ z)
{
    using namespace lif;
    if (blockIdx.x == 0 && threadIdx.x == 0) g_fix_count = 0;

    size_t i4 = (size_t)blockIdx.x * blockDim.x + threadIdx.x;
    int m   = (int)(i4 / (KTOT / 4));
    int col = (int)(i4 % (KTOT / 4)) * 4;
    const float* src = (col < KIN) ? inputs + (size_t)m * KIN + col
                                   : z + (size_t)m * N + (col - KIN);
    float4 x = *(const float4*)src;
    __nv_bfloat162 lo = __nv_bfloat162(__float2bfloat16_rn(x.x), __float2bfloat16_rn(x.y));
    __nv_bfloat162 hi = __nv_bfloat162(__float2bfloat16_rn(x.z), __float2bfloat16_rn(x.w));
    uint2 packed;
    packed.x = *(uint32_t*)&lo;
    packed.y = *(uint32_t*)&hi;
    *(uint2*)(g_Abf + (size_t)m * KTOT + col) = packed;
}

// ============================================================================
// Pass 1b: W^T transpose: Bbf = bf16_rn(W^T), Bt = exact fp32 W^T (fixup).
// ============================================================================
__global__ __launch_bounds__(256) void lif_conv_b(
    const float* __restrict__ w_in, const float* __restrict__ w_rec)
{
    using namespace lif;
    __shared__ float t[32][33];
    const int k0 = blockIdx.x * 32;
    const int n0 = blockIdx.y * 32;
    const int tx = threadIdx.x, ty = threadIdx.y;   // block (32, 8)

    #pragma unroll
    for (int i = 0; i < 4; ++i) {
        int k = k0 + ty + i * 8;
        float w = (k < KIN) ? w_in[(size_t)k * N + n0 + tx]
                            : w_rec[(size_t)(k - KIN) * N + n0 + tx];
        t[ty + i * 8][tx] = w;
    }
    __syncthreads();
    #pragma unroll
    for (int i = 0; i < 4; ++i) {
        int n  = n0 + ty + i * 8;
        float x  = t[tx][ty + i * 8];
        size_t dst = (size_t)n * KTOT + k0 + tx;
        g_Bbf[dst] = __float2bfloat16_rn(x);
        g_Bt[dst]  = x;
    }
}

// ============================================================================
// Pass 2: single-pass bf16 GEMM (unchanged from R15 — at its HMMA floor).
// ============================================================================
__global__ __launch_bounds__(lif::NTHR, 1) void lif_gemm(
    const float* __restrict__ v_in,
    const float* __restrict__ z_in,
    const float* __restrict__ w_rec,
    float* __restrict__ out)
{
    using namespace lif;
    extern __shared__ char smem[];
    const uint32_t sbase = smem_u32(smem);

    const int tid  = threadIdx.x;
    const int lane = tid & 31;
    const int wid  = tid >> 5;
    const int wm   = wid & 1;
    const int wn   = wid >> 1;

    const int row0A = blockIdx.y * BM;
    const int row0B = blockIdx.x * BN;

    float* sdiag = (float*)(smem + DIAG_OFF);
    sdiag[tid] = w_rec[(size_t)(row0B + tid) * (N + 1)];

    float acc[4][8][4];
    #pragma unroll
    for (int mt = 0; mt < 4; ++mt)
        #pragma unroll
        for (int nt = 0; nt < 8; ++nt)
            #pragma unroll
            for (int q = 0; q < 4; ++q) acc[mt][nt][q] = 0.0f;

    auto load_stage = [&](int kk, int st) {
        const uint32_t sb = sbase + st * SLOT_SZ;
        const int k0 = kk * BK;
        #pragma unroll
        for (int i = 0; i < 12; ++i) {
            const int u = tid + i * NTHR;
            if (i < 4) {
                const int row = u >> 3, kq = u & 7;
                cp_async16(sb + sw128((uint32_t)(row * 128 + kq * 16)),
                           g_Abf + (size_t)(row0A + row) * KTOT + k0 + kq * 8);
            } else {
                const int ub = u - 1024;
                const int row = ub >> 3, kq = ub & 7;
                cp_async16(sb + A_TILE + sw128((uint32_t)(row * 128 + kq * 16)),
                           g_Bbf + (size_t)(row0B + row) * KTOT + k0 + kq * 8);
            }
        }
        CP_COMMIT();
    };

    load_stage(0, 0);
    load_stage(1, 1);

    for (int kk = 0; kk < NKK; ++kk) {
        if (kk + 1 < NKK) { CP_WAIT(1); } else { CP_WAIT(0); }
        __syncthreads();
        if (kk + 2 < NKK) load_stage(kk + 2, (kk + 2) % NSTAGE);

        const uint32_t sb = sbase + (kk % NSTAGE) * SLOT_SZ;
        const uint32_t sA = sb;
        const uint32_t sB = sb + A_TILE;

        #pragma unroll
        for (int ks = 0; ks < 4; ++ks) {
            uint32_t a[4][4], b[4][4];
            #pragma unroll
            for (int mt = 0; mt < 4; ++mt)
                ldsm_a(a[mt], sA, wm * 64 + mt * 16, ks, lane);
            #pragma unroll
            for (int nb = 0; nb < 4; ++nb)
                ldsm_b(b[nb], sB, wn * 64 + nb * 16, ks, lane);

            #pragma unroll
            for (int mt = 0; mt < 4; ++mt)
                #pragma unroll
                for (int nt = 0; nt < 8; ++nt)
                    mma_bf16(acc[mt][nt], a[mt],
                             b[nt >> 1][2 * (nt & 1)], b[nt >> 1][2 * (nt & 1) + 1]);
        }
    }

    const float ONE_MD = 1.0f - DECAYF;
    const size_t vout_off = (size_t)M * N;

    const int qrow = lane >> 2;
    const int qcol = 2 * (lane & 3);

    #pragma unroll
    for (int mt = 0; mt < 4; ++mt) {
        #pragma unroll
        for (int half = 0; half < 2; ++half) {
            const int r = row0A + wm * 64 + mt * 16 + half * 8 + qrow;
            #pragma unroll
            for (int nt = 0; nt < 8; ++nt) {
                const int cl = wn * 64 + nt * 8 + qcol;
                const int c  = row0B + cl;
                const size_t g = (size_t)r * N + c;

                const float2 zz = *(const float2*)(z_in + g);
                const float2 vv = *(const float2*)(v_in + g);
                const float a0 = acc[mt][nt][half * 2 + 0];
                const float a1 = acc[mt][nt][half * 2 + 1];

                const float it0 = a0 - zz.x * sdiag[cl];
                const float it1 = a1 - zz.y * sdiag[cl + 1];
                const float nv0 = DECAYF * vv.x + ONE_MD * it0 - zz.x * THRF;
                const float nv1 = DECAYF * vv.y + ONE_MD * it1 - zz.y * THRF;
                const float vs0 = (nv0 - THRF) / THRF;
                const float vs1 = (nv1 - THRF) / THRF;

                *(float2*)(out + g) = make_float2(vs0 > THRF ? 1.0f : 0.0f,
                                                  vs1 > THRF ? 1.0f : 0.0f);
                *(float2*)(out + vout_off + g) = make_float2(nv0, nv1);

                if (fabsf(vs0 - THRF) < EPS_VS) {
                    int s = atomicAdd(&g_fix_count, 1);
                    if (s < FIX_CAP) g_fix_idx[s] = (int)g;
                }
                if (fabsf(vs1 - THRF) < EPS_VS) {
                    int s = atomicAdd(&g_fix_count, 1);
                    if (s < FIX_CAP) g_fix_idx[s] = (int)(g + 1);
                }
            }
        }
    }
}

// ============================================================================
// Pass 3: DP recompute of borderline elements — one warp each, float4 loads
// (48 LDG.128 per element), 2 independent DP accumulators per lane.
// ============================================================================
__global__ __launch_bounds__(256) void lif_fixup(
    const float* __restrict__ inputs,
    const float* __restrict__ v_in,
    const float* __restrict__ z_in,
    const float* __restrict__ w_rec,
    float* __restrict__ out)
{
    using namespace lif;
    const int gtid  = blockIdx.x * blockDim.x + threadIdx.x;
    const int warp  = gtid >> 5;
    const int lane  = gtid & 31;
    const int nwarp = (gridDim.x * blockDim.x) >> 5;

    int cnt = g_fix_count;
    if (cnt > FIX_CAP) cnt = FIX_CAP;

    const double DECAY_D  = (double)DECAYF;
    const double ONE_MD_D = (double)(1.0f - DECAYF);
    const double THR_D    = (double)THRF;
    const size_t vout_off = (size_t)M * N;

    for (int e = warp; e < cnt; e += nwarp) {
        const int idx = g_fix_idx[e];
        const int b = idx / N;
        const int n = idx - b * N;

        const float4* bt4 = (const float4*)(g_Bt + (size_t)n * KTOT);       // 768 f4
        const float4* ai4 = (const float4*)(inputs + (size_t)b * KIN);      // 256 f4
        const float4* az4 = (const float4*)(z_in + (size_t)b * N);          // 512 f4

        double acc0 = 0.0, acc1 = 0.0;
        #pragma unroll
        for (int i = 0; i < 8; ++i) {          // inputs · w_in part
            const float4 a = ai4[lane + 32 * i];
            const float4 w = bt4[lane + 32 * i];
            acc0 += (double)a.x * (double)w.x + (double)a.y * (double)w.y;
            acc1 += (double)a.z * (double)w.z + (double)a.w * (double)w.w;
        }
        #pragma unroll
        for (int i = 0; i < 16; ++i) {         // z · w_rec part
            const float4 a = az4[lane + 32 * i];
            const float4 w = bt4[256 + lane + 32 * i];
            acc0 += (double)a.x * (double)w.x + (double)a.y * (double)w.y;
            acc1 += (double)a.z * (double)w.z + (double)a.w * (double)w.w;
        }
        double acc = acc0 + acc1;
        #pragma unroll
        for (int o = 16; o; o >>= 1)
            acc += __shfl_down_sync(0xFFFFFFFFu, acc, o);

        if (lane == 0) {
            const double zd = (double)z_in[idx];
            const double it = acc - zd * (double)w_rec[(size_t)n * (N + 1)];
            const double nv = DECAY_D * (double)v_in[idx] + ONE_MD_D * it - zd * THR_D;
            const double vs = (nv - THR_D) / THR_D;
            out[idx]            = (vs > THR_D) ? 1.0f : 0.0f;
            out[vout_off + idx] = (float)nv;
        }
    }
}

// ============================================================================
extern "C" void kernel_launch(void* const* d_in, const int* in_sizes, int n_in,
                              void* d_out, int out_size)
{
    (void)in_sizes; (void)n_in; (void)out_size;
    using namespace lif;
    const float* inputs = (const float*)d_in[0];   // [4096, 1024]
    const float* v      = (const float*)d_in[1];   // [4096, 2048]
    const float* z      = (const float*)d_in[2];   // [4096, 2048]
    const float* w_in   = (const float*)d_in[3];   // [1024, 2048]
    const float* w_rec  = (const float*)d_in[4];   // [2048, 2048]
    float* out = (float*)d_out;                    // [2, 4096, 2048] (z then v)

    static bool attr_set = false;
    if (!attr_set) {
        cudaFuncSetAttribute(lif_gemm, cudaFuncAttributeMaxDynamicSharedMemorySize, SMEM_TOTAL);
        attr_set = true;
    }

    lif_conv_a<<<(M * KTOT / 4) / 256, 256>>>(inputs, z);
    lif_conv_b<<<dim3(KTOT / 32, N / 32), dim3(32, 8)>>>(w_in, w_rec);
    lif_gemm<<<dim3(N / BN, M / BM), NTHR, SMEM_TOTAL>>>(v, z, w_rec, out);
    lif_fixup<<<512, 256>>>(inputs, v, z, w_rec, out);
}